// round 14
// baseline (speedup 1.0000x reference)
// AttLayer fused, GB300 (sm_103 PTX: mma.sync tf32 + cp.async).
// out[b,d] = sum_t exp(tanh(x@W + b)·uw)_t * x[b,t,d] / (sum_t exp(...) + eps)
// R13: single-barrier multistage W pipeline (3 ring buffers, 1 syncthreads/chunk),
//      XOR-swizzled x tile (64KB exact), header aliased into W region post-loop.
//      SMEM = 114,688B = 14 x 8KB granules -> clean 2 CTAs/SM.
//      TILE_T=64, 256 thr / 8 warps, warp tile M=32 N=64, zero-CVT mainloop.

#include <cuda_runtime.h>
#include <cstdint>
#include <math.h>

#define DEV __device__ __forceinline__

static constexpr int BATCH  = 64;
static constexpr int TLEN   = 2048;
static constexpr int DIM    = 256;
static constexpr int TILE_T = 64;
static constexpr int NTILES = TLEN / TILE_T;   // 32
static constexpr int KC     = 16;              // K per chunk
static constexpr int NCHUNK = DIM / KC;        // 16
static constexpr int WCHUNK_F = 128 * 32;      // 4096 words = 16KB per chunk
static constexpr int NBUF   = 3;
static constexpr int NTHR   = 256;             // 8 warps

// SMEM layout (bytes): x tile at 0 (64KB, XOR-swizzled), W ring at 64KB.
static constexpr int SMEM_X    = 0;
static constexpr int X_BYTES   = TILE_T * DIM * 4;               // 65536
static constexpr int SMEM_W    = SMEM_X + X_BYTES;               // 65536
static constexpr int SMEM_TOTAL = SMEM_W + NBUF * WCHUNK_F * 4;  // 114688 = 14*8KB
// post-mainloop aliases inside W region:
static constexpr int SMEM_EP   = SMEM_W;                         // 64*4 f = 1KB
static constexpr int SMEM_WEXP = SMEM_W + 1024;                  // 64 f
static constexpr int SMEM_FLAG = SMEM_W + 1280;                  // int
static constexpr int SMEM_BIAS = SMEM_W + 2048;                  // 256 f
static constexpr int SMEM_UW   = SMEM_W + 3072;                  // 256 f

__device__ uint32_t g_Wtf[DIM * DIM];          // fragment-order tf32 W (256KB)
__device__ float g_partial[BATCH * NTILES * DIM];
__device__ float g_S[BATCH * NTILES];
__device__ int   g_cnt[BATCH];                 // zero-init; reset by reducer

DEV uint32_t smem_u32(const void* p) {
    uint32_t a;
    asm("{ .reg .u64 t; cvta.to.shared.u64 t, %1; cvt.u32.u64 %0, t; }"
        : "=r"(a) : "l"(p));
    return a;
}
DEV void cp16(uint32_t saddr, const void* g) {
    asm volatile("cp.async.cg.shared.global [%0], [%1], 16;"
                 :: "r"(saddr), "l"(g) : "memory");
}
DEV void cp_commit() { asm volatile("cp.async.commit_group;" ::: "memory"); }
template <int N> DEV void cp_wait() {
    asm volatile("cp.async.wait_group %0;" :: "n"(N) : "memory");
}
DEV uint32_t f2tf(float f) {
    uint32_t r;
    asm("cvt.rna.tf32.f32 %0, %1;" : "=r"(r) : "f"(f));
    return r;
}
DEV void mma_tf32(float* d, uint32_t a0, uint32_t a1, uint32_t a2, uint32_t a3,
                  uint32_t b0, uint32_t b1) {
    asm volatile(
        "mma.sync.aligned.m16n8k8.row.col.f32.tf32.tf32.f32 "
        "{%0,%1,%2,%3}, {%4,%5,%6,%7}, {%8,%9}, {%0,%1,%2,%3};"
        : "+f"(d[0]), "+f"(d[1]), "+f"(d[2]), "+f"(d[3])
        : "r"(a0), "r"(a1), "r"(a2), "r"(a3), "r"(b0), "r"(b1));
}

// x tile XOR swizzle: word address of element (m, d), m in 0..63, d in 0..255.
// Bank = (d ^ 4*(m&7)) mod 32: A-frag lanes (g,tg) -> tg ^ 4g, bijective -> CF.
DEV uint32_t xadr(int m, int d) { return (uint32_t)(m * 256 + (d ^ ((m & 7) * 4))); }

// ---- prep: W[k][n] fp32 -> g_Wtf fragment-order tf32, KC=16 chunk blocks ----
__global__ void __launch_bounds__(512, 4)
w_prep(const float* __restrict__ W) {
    int i = blockIdx.x * 512 + threadIdx.x;    // 0..65535
    int k = i >> 8, n = i & 255;
    int c = k >> 4, kk = k & 15;
    int s = kk >> 3, h = (kk >> 2) & 1, tg2 = kk & 3;
    int q = n >> 6, j = (n >> 3) & 7, gg = n & 7;
    int r   = ((s * 2 + h) * 8 + gg) * 4 + tg2;
    int col = (q * 8 + j + 16 * (gg & 1) + 4 * tg2) & 31;
    g_Wtf[c * WCHUNK_F + r * 32 + col] = f2tf(W[k * DIM + n]);
}

DEV void load_w_chunk(uint32_t sb, int c, int buf, int tid) {
    // linear 16KB copy: 1024 uint4 / 256 threads = 4 each
    const uint32_t* src = g_Wtf + c * WCHUNK_F;
    const uint32_t dst = sb + (uint32_t)(SMEM_W + buf * WCHUNK_F * 4);
    #pragma unroll
    for (int r = 0; r < 4; ++r) {
        int i = tid + r * NTHR;
        cp16(dst + (uint32_t)i * 16, src + i * 4);
    }
    cp_commit();
}

__global__ void __launch_bounds__(NTHR, 2)
att_fused(const float* __restrict__ x,
          const float* __restrict__ bvec, const float* __restrict__ uw,
          const int* __restrict__ mask, float* __restrict__ out) {
    extern __shared__ char smem[];
    float* sf = (float*)smem;
    const uint32_t sb = smem_u32(smem);

    const int tid = threadIdx.x;
    const int wid = tid >> 5;            // 0..7
    const int lid = tid & 31;
    const int wm  = wid >> 2;            // 0..1 : rows wm*32..+31
    const int wn  = wid & 3;             // 0..3 : cols wn*64..+63
    const int g   = lid >> 2;            // 0..7
    const int tg  = lid & 3;             // 0..3

    const int bt = blockIdx.x;           // 0..2047
    const int b  = bt >> 5;
    const int t0 = (bt & 31) * TILE_T;

    // ---- prologue: cp.async W0,W1 | x fill (LDG->CVT->STS, swizzled) ----
    load_w_chunk(sb, 0, 0, tid);
    load_w_chunk(sb, 1, 1, tid);

    const float* xrow = x + ((size_t)b * TLEN + t0) * DIM;
    float* xs = sf + SMEM_X / 4;
    #pragma unroll
    for (int r = 0; r < 16; ++r) {       // 64*64=4096 float4 / 256 thr
        int i = r * NTHR + tid;
        int m = i >> 6, d0 = (i & 63) * 4;
        float4 v = *(const float4*)(xrow + (size_t)m * DIM + d0);
        uint4 uv;
        uv.x = f2tf(v.x); uv.y = f2tf(v.y); uv.z = f2tf(v.z); uv.w = f2tf(v.w);
        *(uint4*)(xs + xadr(m, d0)) = uv;
    }
    cp_wait<1>();                        // W0 ready (W1 may be in flight)
    __syncthreads();

    // ---- mainloop: 1 barrier per chunk, 3-stage W ring ----
    float acc[2][8][4];
    #pragma unroll
    for (int i = 0; i < 2; ++i)
        #pragma unroll
        for (int j = 0; j < 8; ++j)
            #pragma unroll
            for (int r = 0; r < 4; ++r) acc[i][j][r] = 0.f;

    const uint32_t* xu = (const uint32_t*)xs;
    const int arow0 = wm * 32 + g;
    const int sw4   = (g & 7) * 4;       // x swizzle term for this thread's rows
    const int colb  = (wn * 8 + 16 * (g & 1) + 4 * tg) & 31;
    const int colb4 = (colb + 4) & 31;

    int buf = 0;
    for (int c = 0; c < NCHUNK; ++c) {
        // prefetch chunk c+2 into the slot chunk c-1 used (safe: barrier passed)
        if (c + 2 < NCHUNK) {
            int nb = buf + 2; if (nb >= NBUF) nb -= NBUF;
            load_w_chunk(sb, c + 2, nb, tid);
        }
        const uint32_t* wbu =
            (const uint32_t*)(sf + SMEM_W / 4 + buf * WCHUNK_F);
        #pragma unroll
        for (int s = 0; s < 2; ++s) {    // KC=16 -> 2 k8 steps
            const int col0 = c * KC + s * 8 + tg;
            uint32_t a[2][4];
            #pragma unroll
            for (int i = 0; i < 2; ++i) {
                const int R = arow0 + i * 16;
                a[i][0] = xu[R * 256 + (col0 ^ sw4)];
                a[i][1] = xu[(R + 8) * 256 + (col0 ^ sw4)];
                a[i][2] = xu[R * 256 + ((col0 + 4) ^ sw4)];
                a[i][3] = xu[(R + 8) * 256 + ((col0 + 4) ^ sw4)];
            }
            uint32_t bfr[8][2];
            #pragma unroll
            for (int h = 0; h < 2; ++h) {
                int r = ((s * 2 + h) * 8 + g) * 4 + tg;
                uint4 v0 = *(const uint4*)(wbu + r * 32 + colb);
                uint4 v1 = *(const uint4*)(wbu + r * 32 + colb4);
                bfr[0][h] = v0.x; bfr[1][h] = v0.y; bfr[2][h] = v0.z; bfr[3][h] = v0.w;
                bfr[4][h] = v1.x; bfr[5][h] = v1.y; bfr[6][h] = v1.z; bfr[7][h] = v1.w;
            }
            #pragma unroll
            for (int i = 0; i < 2; ++i)
                #pragma unroll
                for (int j = 0; j < 8; ++j)
                    mma_tf32(acc[i][j], a[i][0], a[i][1], a[i][2], a[i][3],
                             bfr[j][0], bfr[j][1]);
        }
        if (c + 1 < NCHUNK) {
            if (c + 2 < NCHUNK) cp_wait<1>();   // chunk c+1 landed (c+2 in flight)
            else                cp_wait<0>();
            __syncthreads();                    // single barrier per chunk
        }
        if (++buf == NBUF) buf = 0;
    }

    // ---- epilogue: W region repurposed (all warps past mainloop) ----
    __syncthreads();
    sf[SMEM_BIAS / 4 + tid] = bvec[tid];
    sf[SMEM_UW / 4 + tid]   = uw[tid];
    __syncthreads();

    // epi-1: eij partials
    {
        const float* sBias = sf + SMEM_BIAS / 4;
        const float* sUw   = sf + SMEM_UW / 4;
        float* epart       = sf + SMEM_EP / 4;
        #pragma unroll
        for (int i = 0; i < 2; ++i) {
            float rs0 = 0.f, rs1 = 0.f;
            #pragma unroll
            for (int j = 0; j < 8; ++j) {
                const int c0 = wn * 64 + j * 8 + 2 * tg;
                const float b0 = sBias[c0], b1 = sBias[c0 + 1];
                const float u0 = sUw[c0],   u1 = sUw[c0 + 1];
                rs0 += tanhf(acc[i][j][0] + b0) * u0 + tanhf(acc[i][j][1] + b1) * u1;
                rs1 += tanhf(acc[i][j][2] + b0) * u0 + tanhf(acc[i][j][3] + b1) * u1;
            }
            rs0 += __shfl_xor_sync(0xFFFFFFFFu, rs0, 1);
            rs0 += __shfl_xor_sync(0xFFFFFFFFu, rs0, 2);
            rs1 += __shfl_xor_sync(0xFFFFFFFFu, rs1, 1);
            rs1 += __shfl_xor_sync(0xFFFFFFFFu, rs1, 2);
            if (tg == 0) {
                const int r = wm * 32 + i * 16 + g;
                epart[r * 4 + wn]       = rs0;
                epart[(r + 8) * 4 + wn] = rs1;
            }
        }
    }
    __syncthreads();

    // epi-2: softmax-numerator weights
    float* sWexp = sf + SMEM_WEXP / 4;
    if (tid < TILE_T) {
        const float* epart = sf + SMEM_EP / 4;
        float e = epart[tid * 4 + 0] + epart[tid * 4 + 1] +
                  epart[tid * 4 + 2] + epart[tid * 4 + 3];
        sWexp[tid] = expf(e) * (float)mask[(size_t)b * TLEN + t0 + tid];
    }
    __syncthreads();

    // S sum (warp 0, parallel)
    if (tid < 32) {
        float s = sWexp[tid] + sWexp[tid + 32];
        s += __shfl_xor_sync(0xFFFFFFFFu, s, 16);
        s += __shfl_xor_sync(0xFFFFFFFFu, s, 8);
        s += __shfl_xor_sync(0xFFFFFFFFu, s, 4);
        s += __shfl_xor_sync(0xFFFFFFFFu, s, 2);
        s += __shfl_xor_sync(0xFFFFFFFFu, s, 1);
        if (tid == 0) g_S[bt] = s;
    }

    // epi-3: weighted column sum from resident x tile (tf32 values, swizzled)
    {
        float a0 = 0.f, a1 = 0.f;
        #pragma unroll 8
        for (int m = 0; m < TILE_T; m += 2) {
            a0 = fmaf(sWexp[m],     xs[xadr(m,     tid)], a0);
            a1 = fmaf(sWexp[m + 1], xs[xadr(m + 1, tid)], a1);
        }
        g_partial[(size_t)bt * DIM + tid] = a0 + a1;
    }

    // ---- fused tail: last CTA of each batch reduces (deterministic order) ----
    __threadfence();
    __syncthreads();
    int* sflag = (int*)(smem + SMEM_FLAG);
    if (tid == 0) {
        int old = atomicAdd(&g_cnt[b], 1);
        *sflag = (old == NTILES - 1);
    }
    __syncthreads();
    if (*sflag) {
        __threadfence();   // acquire: see all tiles' partials
        float s = 0.f, p = 0.f;
        #pragma unroll
        for (int t = 0; t < NTILES; ++t) {
            p += g_partial[(size_t)(b * NTILES + t) * DIM + tid];
            s += g_S[b * NTILES + t];
        }
        out[b * DIM + tid] = p / (s + 1e-7f);
        if (tid == 0) g_cnt[b] = 0;   // reset for next graph replay
    }
}

extern "C" void kernel_launch(void* const* d_in, const int* in_sizes, int n_in,
                              void* d_out, int out_size) {
    const float* x    = (const float*)d_in[0];
    const float* W    = (const float*)d_in[1];
    const float* bvec = (const float*)d_in[2];
    const float* uw   = (const float*)d_in[3];
    const int*   mask = (const int*)d_in[4];
    float* out = (float*)d_out;

    w_prep<<<DIM * DIM / 512, 512>>>(W);
    cudaFuncSetAttribute(att_fused, cudaFuncAttributeMaxDynamicSharedMemorySize,
                         SMEM_TOTAL);
    att_fused<<<BATCH * NTILES, NTHR, SMEM_TOTAL>>>(x, bvec, uw, mask, out);
}

// round 15
// speedup vs baseline: 1.0920x; 1.0920x over previous
// AttLayer fused, GB300 (sm_103 PTX: mma.sync tf32 + cp.async).
// out[b,d] = sum_t exp(tanh(x@W + b)·uw)_t * x[b,t,d] / (sum_t exp(...) + eps)
// R14: FULLY UNROLLED mainloop (16 chunks, ring indices constant-folded) +
//      per-thread base-pointer/immediate addressing -> near-zero mainloop ALU.
//      Otherwise identical to R13: 3-stage W ring, 1 barrier/chunk, XOR-swizzled
//      64KB x tile, epilogue aliased into W region, fused deterministic tail.

#include <cuda_runtime.h>
#include <cstdint>
#include <math.h>

#define DEV __device__ __forceinline__

static constexpr int BATCH  = 64;
static constexpr int TLEN   = 2048;
static constexpr int DIM    = 256;
static constexpr int TILE_T = 64;
static constexpr int NTILES = TLEN / TILE_T;   // 32
static constexpr int KC     = 16;              // K per chunk
static constexpr int NCHUNK = DIM / KC;        // 16
static constexpr int WCHUNK_F = 128 * 32;      // 4096 words = 16KB per chunk
static constexpr int NBUF   = 3;
static constexpr int NTHR   = 256;             // 8 warps

// SMEM layout (bytes): x tile at 0 (64KB, XOR-swizzled), W ring at 64KB.
static constexpr int SMEM_X    = 0;
static constexpr int X_BYTES   = TILE_T * DIM * 4;               // 65536
static constexpr int SMEM_W    = SMEM_X + X_BYTES;               // 65536
static constexpr int SMEM_TOTAL = SMEM_W + NBUF * WCHUNK_F * 4;  // 114688
// post-mainloop aliases inside W region:
static constexpr int SMEM_EP   = SMEM_W;                         // 64*4 f
static constexpr int SMEM_WEXP = SMEM_W + 1024;                  // 64 f
static constexpr int SMEM_FLAG = SMEM_W + 1280;                  // int
static constexpr int SMEM_BIAS = SMEM_W + 2048;                  // 256 f
static constexpr int SMEM_UW   = SMEM_W + 3072;                  // 256 f

__device__ uint32_t g_Wtf[DIM * DIM];          // fragment-order tf32 W (256KB)
__device__ float g_partial[BATCH * NTILES * DIM];
__device__ float g_S[BATCH * NTILES];
__device__ int   g_cnt[BATCH];                 // zero-init; reset by reducer

DEV uint32_t smem_u32(const void* p) {
    uint32_t a;
    asm("{ .reg .u64 t; cvta.to.shared.u64 t, %1; cvt.u32.u64 %0, t; }"
        : "=r"(a) : "l"(p));
    return a;
}
DEV void cp16(uint32_t saddr, const void* g) {
    asm volatile("cp.async.cg.shared.global [%0], [%1], 16;"
                 :: "r"(saddr), "l"(g) : "memory");
}
DEV void cp_commit() { asm volatile("cp.async.commit_group;" ::: "memory"); }
template <int N> DEV void cp_wait() {
    asm volatile("cp.async.wait_group %0;" :: "n"(N) : "memory");
}
DEV uint32_t f2tf(float f) {
    uint32_t r;
    asm("cvt.rna.tf32.f32 %0, %1;" : "=r"(r) : "f"(f));
    return r;
}
DEV void mma_tf32(float* d, uint32_t a0, uint32_t a1, uint32_t a2, uint32_t a3,
                  uint32_t b0, uint32_t b1) {
    asm volatile(
        "mma.sync.aligned.m16n8k8.row.col.f32.tf32.tf32.f32 "
        "{%0,%1,%2,%3}, {%4,%5,%6,%7}, {%8,%9}, {%0,%1,%2,%3};"
        : "+f"(d[0]), "+f"(d[1]), "+f"(d[2]), "+f"(d[3])
        : "r"(a0), "r"(a1), "r"(a2), "r"(a3), "r"(b0), "r"(b1));
}

// x tile XOR swizzle: word address of element (m, d).
// Bank = (d ^ 4*(m&7)) mod 32: A-frag lanes conflict-free; STS.128/epi reads CF.
DEV uint32_t xadr(int m, int d) { return (uint32_t)(m * 256 + (d ^ ((m & 7) * 4))); }

// ---- prep: W[k][n] fp32 -> g_Wtf fragment-order tf32, KC=16 chunk blocks ----
__global__ void __launch_bounds__(512, 4)
w_prep(const float* __restrict__ W) {
    int i = blockIdx.x * 512 + threadIdx.x;    // 0..65535
    int k = i >> 8, n = i & 255;
    int c = k >> 4, kk = k & 15;
    int s = kk >> 3, h = (kk >> 2) & 1, tg2 = kk & 3;
    int q = n >> 6, j = (n >> 3) & 7, gg = n & 7;
    int r   = ((s * 2 + h) * 8 + gg) * 4 + tg2;
    int col = (q * 8 + j + 16 * (gg & 1) + 4 * tg2) & 31;
    g_Wtf[c * WCHUNK_F + r * 32 + col] = f2tf(W[k * DIM + n]);
}

DEV void load_w_chunk(uint32_t sb, int c, int buf, int tid) {
    // linear 16KB copy: 1024 uint4 / 256 threads = 4 each
    const uint32_t* src = g_Wtf + c * WCHUNK_F;
    const uint32_t dst = sb + (uint32_t)(SMEM_W + buf * WCHUNK_F * 4);
    #pragma unroll
    for (int r = 0; r < 4; ++r) {
        int i = tid + r * NTHR;
        cp16(dst + (uint32_t)i * 16, src + i * 4);
    }
    cp_commit();
}

__global__ void __launch_bounds__(NTHR, 2)
att_fused(const float* __restrict__ x,
          const float* __restrict__ bvec, const float* __restrict__ uw,
          const int* __restrict__ mask, float* __restrict__ out) {
    extern __shared__ char smem[];
    float* sf = (float*)smem;
    const uint32_t sb = smem_u32(smem);

    const int tid = threadIdx.x;
    const int wid = tid >> 5;            // 0..7
    const int lid = tid & 31;
    const int wm  = wid >> 2;            // 0..1 : rows wm*32..+31
    const int wn  = wid & 3;             // 0..3 : cols wn*64..+63
    const int g   = lid >> 2;            // 0..7
    const int tg  = lid & 3;             // 0..3

    const int bt = blockIdx.x;           // 0..2047
    const int b  = bt >> 5;
    const int t0 = (bt & 31) * TILE_T;

    // ---- prologue: cp.async W0,W1 | x fill (LDG->CVT->STS, swizzled) ----
    load_w_chunk(sb, 0, 0, tid);
    load_w_chunk(sb, 1, 1, tid);

    const float* xrow = x + ((size_t)b * TLEN + t0) * DIM;
    float* xs = sf + SMEM_X / 4;
    #pragma unroll
    for (int r = 0; r < 16; ++r) {       // 64*64=4096 float4 / 256 thr
        int i = r * NTHR + tid;
        int m = i >> 6, d0 = (i & 63) * 4;
        float4 v = *(const float4*)(xrow + (size_t)m * DIM + d0);
        uint4 uv;
        uv.x = f2tf(v.x); uv.y = f2tf(v.y); uv.z = f2tf(v.z); uv.w = f2tf(v.w);
        *(uint4*)(xs + xadr(m, d0)) = uv;
    }
    cp_wait<1>();                        // W0 ready (W1 may be in flight)
    __syncthreads();

    // ---- mainloop: FULLY UNROLLED, 3-stage W ring, 1 barrier/chunk ----
    float acc[2][8][4];
    #pragma unroll
    for (int i = 0; i < 2; ++i)
        #pragma unroll
        for (int j = 0; j < 8; ++j)
            #pragma unroll
            for (int r = 0; r < 4; ++r) acc[i][j][r] = 0.f;

    // per-thread bases (computed once; inner addressing = base + immediates)
    const uint32_t* xu = (const uint32_t*)xs;
    const int arow0 = wm * 32 + g;
    const uint32_t* abase = xu + arow0 * 256 + tg;          // + (X^sw4) per step
    const int sw4   = (g & 7) * 4;
    const int colb  = (wn * 8 + 16 * (g & 1) + 4 * tg) & 31;
    const int colb4 = (colb + 4) & 31;
    const int boff  = (4 * g + tg) * 32;                    // r*32 thread part
    const uint32_t* wbase = (const uint32_t*)(sf + SMEM_W / 4);

    #pragma unroll
    for (int c = 0; c < NCHUNK; ++c) {
        const int buf = c % NBUF;                           // compile-time
        if (c + 2 < NCHUNK) {
            const int nb = (c + 2) % NBUF;                  // compile-time
            load_w_chunk(sb, c + 2, nb, tid);
        }
        const uint32_t* wbu = wbase + buf * WCHUNK_F + boff;
        #pragma unroll
        for (int s = 0; s < 2; ++s) {
            // A: offset = ((c*16+s*8) ^ sw4) + tg ; rows via immediates
            const int aoff = (c * KC + s * 8) ^ sw4;        // 1 LOP3/step
            const uint32_t* ap = abase + aoff;
            const int a4 = (4 ^ sw4) - (0 ^ sw4);           // = +4 or -4 (const per thread)
            uint32_t a[2][4];
            #pragma unroll
            for (int i = 0; i < 2; ++i) {
                const uint32_t* r0 = ap + (i * 16) * 256;
                a[i][0] = r0[0];
                a[i][1] = r0[8 * 256];
                a[i][2] = r0[a4];
                a[i][3] = r0[8 * 256 + a4];
            }
            // B: base + compile-time (s*2+h)*32*... immediates
            uint32_t bfr[8][2];
            #pragma unroll
            for (int h = 0; h < 2; ++h) {
                const uint32_t* bp = wbu + (s * 2 + h) * 8 * 4 * 32;
                uint4 v0 = *(const uint4*)(bp + colb);
                uint4 v1 = *(const uint4*)(bp + colb4);
                bfr[0][h] = v0.x; bfr[1][h] = v0.y; bfr[2][h] = v0.z; bfr[3][h] = v0.w;
                bfr[4][h] = v1.x; bfr[5][h] = v1.y; bfr[6][h] = v1.z; bfr[7][h] = v1.w;
            }
            #pragma unroll
            for (int i = 0; i < 2; ++i)
                #pragma unroll
                for (int j = 0; j < 8; ++j)
                    mma_tf32(acc[i][j], a[i][0], a[i][1], a[i][2], a[i][3],
                             bfr[j][0], bfr[j][1]);
        }
        if (c + 1 < NCHUNK) {
            if (c + 2 < NCHUNK) cp_wait<1>();
            else                cp_wait<0>();
            __syncthreads();
        }
    }

    // ---- epilogue: W region repurposed (all warps past mainloop) ----
    __syncthreads();
    sf[SMEM_BIAS / 4 + tid] = bvec[tid];
    sf[SMEM_UW / 4 + tid]   = uw[tid];
    __syncthreads();

    // epi-1: eij partials
    {
        const float* sBias = sf + SMEM_BIAS / 4;
        const float* sUw   = sf + SMEM_UW / 4;
        float* epart       = sf + SMEM_EP / 4;
        #pragma unroll
        for (int i = 0; i < 2; ++i) {
            float rs0 = 0.f, rs1 = 0.f;
            #pragma unroll
            for (int j = 0; j < 8; ++j) {
                const int c0 = wn * 64 + j * 8 + 2 * tg;
                const float b0 = sBias[c0], b1 = sBias[c0 + 1];
                const float u0 = sUw[c0],   u1 = sUw[c0 + 1];
                rs0 += tanhf(acc[i][j][0] + b0) * u0 + tanhf(acc[i][j][1] + b1) * u1;
                rs1 += tanhf(acc[i][j][2] + b0) * u0 + tanhf(acc[i][j][3] + b1) * u1;
            }
            rs0 += __shfl_xor_sync(0xFFFFFFFFu, rs0, 1);
            rs0 += __shfl_xor_sync(0xFFFFFFFFu, rs0, 2);
            rs1 += __shfl_xor_sync(0xFFFFFFFFu, rs1, 1);
            rs1 += __shfl_xor_sync(0xFFFFFFFFu, rs1, 2);
            if (tg == 0) {
                const int r = wm * 32 + i * 16 + g;
                epart[r * 4 + wn]       = rs0;
                epart[(r + 8) * 4 + wn] = rs1;
            }
        }
    }
    __syncthreads();

    // epi-2: softmax-numerator weights
    float* sWexp = sf + SMEM_WEXP / 4;
    if (tid < TILE_T) {
        const float* epart = sf + SMEM_EP / 4;
        float e = epart[tid * 4 + 0] + epart[tid * 4 + 1] +
                  epart[tid * 4 + 2] + epart[tid * 4 + 3];
        sWexp[tid] = expf(e) * (float)mask[(size_t)b * TLEN + t0 + tid];
    }
    __syncthreads();

    // S sum (warp 0, parallel)
    if (tid < 32) {
        float s = sWexp[tid] + sWexp[tid + 32];
        s += __shfl_xor_sync(0xFFFFFFFFu, s, 16);
        s += __shfl_xor_sync(0xFFFFFFFFu, s, 8);
        s += __shfl_xor_sync(0xFFFFFFFFu, s, 4);
        s += __shfl_xor_sync(0xFFFFFFFFu, s, 2);
        s += __shfl_xor_sync(0xFFFFFFFFu, s, 1);
        if (tid == 0) g_S[bt] = s;
    }

    // epi-3: weighted column sum from resident x tile (tf32 values, swizzled)
    {
        float a0 = 0.f, a1 = 0.f;
        #pragma unroll 8
        for (int m = 0; m < TILE_T; m += 2) {
            a0 = fmaf(sWexp[m],     xs[xadr(m,     tid)], a0);
            a1 = fmaf(sWexp[m + 1], xs[xadr(m + 1, tid)], a1);
        }
        g_partial[(size_t)bt * DIM + tid] = a0 + a1;
    }

    // ---- fused tail: last CTA of each batch reduces (deterministic order) ----
    __threadfence();
    __syncthreads();
    int* sflag = (int*)(smem + SMEM_FLAG);
    if (tid == 0) {
        int old = atomicAdd(&g_cnt[b], 1);
        *sflag = (old == NTILES - 1);
    }
    __syncthreads();
    if (*sflag) {
        __threadfence();   // acquire: see all tiles' partials
        float s = 0.f, p = 0.f;
        #pragma unroll
        for (int t = 0; t < NTILES; ++t) {
            p += g_partial[(size_t)(b * NTILES + t) * DIM + tid];
            s += g_S[b * NTILES + t];
        }
        out[b * DIM + tid] = p / (s + 1e-7f);
        if (tid == 0) g_cnt[b] = 0;   // reset for next graph replay
    }
}

extern "C" void kernel_launch(void* const* d_in, const int* in_sizes, int n_in,
                              void* d_out, int out_size) {
    const float* x    = (const float*)d_in[0];
    const float* W    = (const float*)d_in[1];
    const float* bvec = (const float*)d_in[2];
    const float* uw   = (const float*)d_in[3];
    const int*   mask = (const int*)d_in[4];
    float* out = (float*)d_out;

    w_prep<<<DIM * DIM / 512, 512>>>(W);
    cudaFuncSetAttribute(att_fused, cudaFuncAttributeMaxDynamicSharedMemorySize,
                         SMEM_TOTAL);
    att_fused<<<BATCH * NTILES, NTHR, SMEM_TOTAL>>>(x, bvec, uw, mask, out);
}

// round 16
// speedup vs baseline: 1.2005x; 1.0993x over previous
// AttLayer fused, GB300 (sm_103 PTX: mma.sync tf32 + cp.async).
// out[b,d] = sum_t exp(tanh(x@W + b)·uw)_t * x[b,t,d] / (sum_t exp(...) + eps)
// R15: R14 winner + tanh.approx.f32 in epilogue-1 (64 HW tanh per thread instead
//      of 64 polynomial expansions on the fma pipe). Everything else unchanged:
//      fully-unrolled zero-ALU mainloop, 3-stage W ring, 1 barrier/chunk,
//      XOR-swizzled 64KB x tile, epilogue aliased into W region, fused tail.

#include <cuda_runtime.h>
#include <cstdint>
#include <math.h>

#define DEV __device__ __forceinline__

static constexpr int BATCH  = 64;
static constexpr int TLEN   = 2048;
static constexpr int DIM    = 256;
static constexpr int TILE_T = 64;
static constexpr int NTILES = TLEN / TILE_T;   // 32
static constexpr int KC     = 16;              // K per chunk
static constexpr int NCHUNK = DIM / KC;        // 16
static constexpr int WCHUNK_F = 128 * 32;      // 4096 words = 16KB per chunk
static constexpr int NBUF   = 3;
static constexpr int NTHR   = 256;             // 8 warps

// SMEM layout (bytes): x tile at 0 (64KB, XOR-swizzled), W ring at 64KB.
static constexpr int SMEM_X    = 0;
static constexpr int X_BYTES   = TILE_T * DIM * 4;               // 65536
static constexpr int SMEM_W    = SMEM_X + X_BYTES;               // 65536
static constexpr int SMEM_TOTAL = SMEM_W + NBUF * WCHUNK_F * 4;  // 114688
// post-mainloop aliases inside W region:
static constexpr int SMEM_EP   = SMEM_W;                         // 64*4 f
static constexpr int SMEM_WEXP = SMEM_W + 1024;                  // 64 f
static constexpr int SMEM_FLAG = SMEM_W + 1280;                  // int
static constexpr int SMEM_BIAS = SMEM_W + 2048;                  // 256 f
static constexpr int SMEM_UW   = SMEM_W + 3072;                  // 256 f

__device__ uint32_t g_Wtf[DIM * DIM];          // fragment-order tf32 W (256KB)
__device__ float g_partial[BATCH * NTILES * DIM];
__device__ float g_S[BATCH * NTILES];
__device__ int   g_cnt[BATCH];                 // zero-init; reset by reducer

DEV uint32_t smem_u32(const void* p) {
    uint32_t a;
    asm("{ .reg .u64 t; cvta.to.shared.u64 t, %1; cvt.u32.u64 %0, t; }"
        : "=r"(a) : "l"(p));
    return a;
}
DEV void cp16(uint32_t saddr, const void* g) {
    asm volatile("cp.async.cg.shared.global [%0], [%1], 16;"
                 :: "r"(saddr), "l"(g) : "memory");
}
DEV void cp_commit() { asm volatile("cp.async.commit_group;" ::: "memory"); }
template <int N> DEV void cp_wait() {
    asm volatile("cp.async.wait_group %0;" :: "n"(N) : "memory");
}
DEV uint32_t f2tf(float f) {
    uint32_t r;
    asm("cvt.rna.tf32.f32 %0, %1;" : "=r"(r) : "f"(f));
    return r;
}
DEV float tanh_hw(float f) {
    float r;
    asm("tanh.approx.f32 %0, %1;" : "=f"(r) : "f"(f));
    return r;
}
DEV void mma_tf32(float* d, uint32_t a0, uint32_t a1, uint32_t a2, uint32_t a3,
                  uint32_t b0, uint32_t b1) {
    asm volatile(
        "mma.sync.aligned.m16n8k8.row.col.f32.tf32.tf32.f32 "
        "{%0,%1,%2,%3}, {%4,%5,%6,%7}, {%8,%9}, {%0,%1,%2,%3};"
        : "+f"(d[0]), "+f"(d[1]), "+f"(d[2]), "+f"(d[3])
        : "r"(a0), "r"(a1), "r"(a2), "r"(a3), "r"(b0), "r"(b1));
}

// x tile XOR swizzle: word address of element (m, d).
DEV uint32_t xadr(int m, int d) { return (uint32_t)(m * 256 + (d ^ ((m & 7) * 4))); }

// ---- prep: W[k][n] fp32 -> g_Wtf fragment-order tf32, KC=16 chunk blocks ----
__global__ void __launch_bounds__(512, 4)
w_prep(const float* __restrict__ W) {
    int i = blockIdx.x * 512 + threadIdx.x;    // 0..65535
    int k = i >> 8, n = i & 255;
    int c = k >> 4, kk = k & 15;
    int s = kk >> 3, h = (kk >> 2) & 1, tg2 = kk & 3;
    int q = n >> 6, j = (n >> 3) & 7, gg = n & 7;
    int r   = ((s * 2 + h) * 8 + gg) * 4 + tg2;
    int col = (q * 8 + j + 16 * (gg & 1) + 4 * tg2) & 31;
    g_Wtf[c * WCHUNK_F + r * 32 + col] = f2tf(W[k * DIM + n]);
}

DEV void load_w_chunk(uint32_t sb, int c, int buf, int tid) {
    const uint32_t* src = g_Wtf + c * WCHUNK_F;
    const uint32_t dst = sb + (uint32_t)(SMEM_W + buf * WCHUNK_F * 4);
    #pragma unroll
    for (int r = 0; r < 4; ++r) {
        int i = tid + r * NTHR;
        cp16(dst + (uint32_t)i * 16, src + i * 4);
    }
    cp_commit();
}

__global__ void __launch_bounds__(NTHR, 2)
att_fused(const float* __restrict__ x,
          const float* __restrict__ bvec, const float* __restrict__ uw,
          const int* __restrict__ mask, float* __restrict__ out) {
    extern __shared__ char smem[];
    float* sf = (float*)smem;
    const uint32_t sb = smem_u32(smem);

    const int tid = threadIdx.x;
    const int wid = tid >> 5;            // 0..7
    const int lid = tid & 31;
    const int wm  = wid >> 2;            // 0..1 : rows wm*32..+31
    const int wn  = wid & 3;             // 0..3 : cols wn*64..+63
    const int g   = lid >> 2;            // 0..7
    const int tg  = lid & 3;             // 0..3

    const int bt = blockIdx.x;           // 0..2047
    const int b  = bt >> 5;
    const int t0 = (bt & 31) * TILE_T;

    // ---- prologue: cp.async W0,W1 | x fill (LDG->CVT->STS, swizzled) ----
    load_w_chunk(sb, 0, 0, tid);
    load_w_chunk(sb, 1, 1, tid);

    const float* xrow = x + ((size_t)b * TLEN + t0) * DIM;
    float* xs = sf + SMEM_X / 4;
    #pragma unroll
    for (int r = 0; r < 16; ++r) {       // 64*64=4096 float4 / 256 thr
        int i = r * NTHR + tid;
        int m = i >> 6, d0 = (i & 63) * 4;
        float4 v = *(const float4*)(xrow + (size_t)m * DIM + d0);
        uint4 uv;
        uv.x = f2tf(v.x); uv.y = f2tf(v.y); uv.z = f2tf(v.z); uv.w = f2tf(v.w);
        *(uint4*)(xs + xadr(m, d0)) = uv;
    }
    cp_wait<1>();                        // W0 ready (W1 may be in flight)
    __syncthreads();

    // ---- mainloop: FULLY UNROLLED, 3-stage W ring, 1 barrier/chunk ----
    float acc[2][8][4];
    #pragma unroll
    for (int i = 0; i < 2; ++i)
        #pragma unroll
        for (int j = 0; j < 8; ++j)
            #pragma unroll
            for (int r = 0; r < 4; ++r) acc[i][j][r] = 0.f;

    const uint32_t* xu = (const uint32_t*)xs;
    const int arow0 = wm * 32 + g;
    const uint32_t* abase = xu + arow0 * 256 + tg;
    const int sw4   = (g & 7) * 4;
    const int colb  = (wn * 8 + 16 * (g & 1) + 4 * tg) & 31;
    const int colb4 = (colb + 4) & 31;
    const int boff  = (4 * g + tg) * 32;
    const uint32_t* wbase = (const uint32_t*)(sf + SMEM_W / 4);

    #pragma unroll
    for (int c = 0; c < NCHUNK; ++c) {
        const int buf = c % NBUF;                           // compile-time
        if (c + 2 < NCHUNK) {
            const int nb = (c + 2) % NBUF;                  // compile-time
            load_w_chunk(sb, c + 2, nb, tid);
        }
        const uint32_t* wbu = wbase + buf * WCHUNK_F + boff;
        #pragma unroll
        for (int s = 0; s < 2; ++s) {
            const int aoff = (c * KC + s * 8) ^ sw4;        // 1 LOP3/step
            const uint32_t* ap = abase + aoff;
            const int a4 = (4 ^ sw4) - (0 ^ sw4);           // +-4, const/thread
            uint32_t a[2][4];
            #pragma unroll
            for (int i = 0; i < 2; ++i) {
                const uint32_t* r0 = ap + (i * 16) * 256;
                a[i][0] = r0[0];
                a[i][1] = r0[8 * 256];
                a[i][2] = r0[a4];
                a[i][3] = r0[8 * 256 + a4];
            }
            uint32_t bfr[8][2];
            #pragma unroll
            for (int h = 0; h < 2; ++h) {
                const uint32_t* bp = wbu + (s * 2 + h) * 8 * 4 * 32;
                uint4 v0 = *(const uint4*)(bp + colb);
                uint4 v1 = *(const uint4*)(bp + colb4);
                bfr[0][h] = v0.x; bfr[1][h] = v0.y; bfr[2][h] = v0.z; bfr[3][h] = v0.w;
                bfr[4][h] = v1.x; bfr[5][h] = v1.y; bfr[6][h] = v1.z; bfr[7][h] = v1.w;
            }
            #pragma unroll
            for (int i = 0; i < 2; ++i)
                #pragma unroll
                for (int j = 0; j < 8; ++j)
                    mma_tf32(acc[i][j], a[i][0], a[i][1], a[i][2], a[i][3],
                             bfr[j][0], bfr[j][1]);
        }
        if (c + 1 < NCHUNK) {
            if (c + 2 < NCHUNK) cp_wait<1>();
            else                cp_wait<0>();
            __syncthreads();
        }
    }

    // ---- epilogue: W region repurposed (all warps past mainloop) ----
    __syncthreads();
    sf[SMEM_BIAS / 4 + tid] = bvec[tid];
    sf[SMEM_UW / 4 + tid]   = uw[tid];
    __syncthreads();

    // epi-1: eij partials (HW tanh.approx)
    {
        const float* sBias = sf + SMEM_BIAS / 4;
        const float* sUw   = sf + SMEM_UW / 4;
        float* epart       = sf + SMEM_EP / 4;
        #pragma unroll
        for (int i = 0; i < 2; ++i) {
            float rs0 = 0.f, rs1 = 0.f;
            #pragma unroll
            for (int j = 0; j < 8; ++j) {
                const int c0 = wn * 64 + j * 8 + 2 * tg;
                const float b0 = sBias[c0], b1 = sBias[c0 + 1];
                const float u0 = sUw[c0],   u1 = sUw[c0 + 1];
                rs0 += tanh_hw(acc[i][j][0] + b0) * u0 + tanh_hw(acc[i][j][1] + b1) * u1;
                rs1 += tanh_hw(acc[i][j][2] + b0) * u0 + tanh_hw(acc[i][j][3] + b1) * u1;
            }
            rs0 += __shfl_xor_sync(0xFFFFFFFFu, rs0, 1);
            rs0 += __shfl_xor_sync(0xFFFFFFFFu, rs0, 2);
            rs1 += __shfl_xor_sync(0xFFFFFFFFu, rs1, 1);
            rs1 += __shfl_xor_sync(0xFFFFFFFFu, rs1, 2);
            if (tg == 0) {
                const int r = wm * 32 + i * 16 + g;
                epart[r * 4 + wn]       = rs0;
                epart[(r + 8) * 4 + wn] = rs1;
            }
        }
    }
    __syncthreads();

    // epi-2: softmax-numerator weights
    float* sWexp = sf + SMEM_WEXP / 4;
    if (tid < TILE_T) {
        const float* epart = sf + SMEM_EP / 4;
        float e = epart[tid * 4 + 0] + epart[tid * 4 + 1] +
                  epart[tid * 4 + 2] + epart[tid * 4 + 3];
        sWexp[tid] = expf(e) * (float)mask[(size_t)b * TLEN + t0 + tid];
    }
    __syncthreads();

    // S sum (warp 0, parallel)
    if (tid < 32) {
        float s = sWexp[tid] + sWexp[tid + 32];
        s += __shfl_xor_sync(0xFFFFFFFFu, s, 16);
        s += __shfl_xor_sync(0xFFFFFFFFu, s, 8);
        s += __shfl_xor_sync(0xFFFFFFFFu, s, 4);
        s += __shfl_xor_sync(0xFFFFFFFFu, s, 2);
        s += __shfl_xor_sync(0xFFFFFFFFu, s, 1);
        if (tid == 0) g_S[bt] = s;
    }

    // epi-3: weighted column sum from resident x tile (tf32 values, swizzled)
    {
        float a0 = 0.f, a1 = 0.f;
        #pragma unroll 8
        for (int m = 0; m < TILE_T; m += 2) {
            a0 = fmaf(sWexp[m],     xs[xadr(m,     tid)], a0);
            a1 = fmaf(sWexp[m + 1], xs[xadr(m + 1, tid)], a1);
        }
        g_partial[(size_t)bt * DIM + tid] = a0 + a1;
    }

    // ---- fused tail: last CTA of each batch reduces (deterministic order) ----
    __threadfence();
    __syncthreads();
    int* sflag = (int*)(smem + SMEM_FLAG);
    if (tid == 0) {
        int old = atomicAdd(&g_cnt[b], 1);
        *sflag = (old == NTILES - 1);
    }
    __syncthreads();
    if (*sflag) {
        __threadfence();   // acquire: see all tiles' partials
        float s = 0.f, p = 0.f;
        #pragma unroll
        for (int t = 0; t < NTILES; ++t) {
            p += g_partial[(size_t)(b * NTILES + t) * DIM + tid];
            s += g_S[b * NTILES + t];
        }
        out[b * DIM + tid] = p / (s + 1e-7f);
        if (tid == 0) g_cnt[b] = 0;   // reset for next graph replay
    }
}

extern "C" void kernel_launch(void* const* d_in, const int* in_sizes, int n_in,
                              void* d_out, int out_size) {
    const float* x    = (const float*)d_in[0];
    const float* W    = (const float*)d_in[1];
    const float* bvec = (const float*)d_in[2];
    const float* uw   = (const float*)d_in[3];
    const int*   mask = (const int*)d_in[4];
    float* out = (float*)d_out;

    w_prep<<<DIM * DIM / 512, 512>>>(W);
    cudaFuncSetAttribute(att_fused, cudaFuncAttributeMaxDynamicSharedMemorySize,
                         SMEM_TOTAL);
    att_fused<<<BATCH * NTILES, NTHR, SMEM_TOTAL>>>(x, bvec, uw, mask, out);
}